// round 1
// baseline (speedup 1.0000x reference)
#include <cuda_runtime.h>
#include <cuda_fp16.h>

#define INPUT_DIM 20000
#define UNITS     4096
#define NNZ       800000
#define BATCH     1024

// ---------------- scratch (no allocations allowed) ----------------
__device__ int    g_col_cnt[UNITS];
__device__ int    g_col_off[UNITS + 1];
__device__ int    g_rows[NNZ];
__device__ float  g_vals[NNZ];
__device__ __half g_xT[(size_t)INPUT_DIM * BATCH];   // 41 MB, fits L2
__device__ float  g_outT[(size_t)UNITS * BATCH];     // 16.8 MB

// ---------------- 1. zero column counters ----------------
__global__ void k_zero() {
    int i = blockIdx.x * blockDim.x + threadIdx.x;
    if (i < UNITS) g_col_cnt[i] = 0;
}

// ---------------- 2. column histogram (smem privatized) ----------------
__global__ void __launch_bounds__(256) k_hist(const int* __restrict__ nz) {
    __shared__ int h[UNITS];
    for (int i = threadIdx.x; i < UNITS; i += blockDim.x) h[i] = 0;
    __syncthreads();
    for (int i = blockIdx.x * blockDim.x + threadIdx.x; i < NNZ;
         i += gridDim.x * blockDim.x) {
        atomicAdd(&h[nz[2 * i + 1]], 1);
    }
    __syncthreads();
    for (int i = threadIdx.x; i < UNITS; i += blockDim.x)
        if (h[i]) atomicAdd(&g_col_cnt[i], h[i]);
}

// ---------------- 3. exclusive scan of 4096 counts (one block) ----------------
__global__ void __launch_bounds__(1024) k_scan() {
    __shared__ int s[1024];
    int t = threadIdx.x;
    int4 c = *reinterpret_cast<int4*>(&g_col_cnt[t * 4]);
    int sum = c.x + c.y + c.z + c.w;
    s[t] = sum;
    __syncthreads();
    for (int off = 1; off < 1024; off <<= 1) {
        int v = (t >= off) ? s[t - off] : 0;
        __syncthreads();
        s[t] += v;
        __syncthreads();
    }
    int o = s[t] - sum;  // exclusive prefix of this group of 4
    g_col_off[t * 4 + 0] = o;  o += c.x;
    g_col_off[t * 4 + 1] = o;  o += c.y;
    g_col_off[t * 4 + 2] = o;  o += c.z;
    g_col_off[t * 4 + 3] = o;
    if (t == 1023) g_col_off[UNITS] = s[1023];
    // reset counters: reused as scatter cursors
    int4 z = make_int4(0, 0, 0, 0);
    *reinterpret_cast<int4*>(&g_col_cnt[t * 4]) = z;
}

// ---------------- 4. scatter into CSC ----------------
__global__ void __launch_bounds__(256) k_scatter(const int* __restrict__ nz,
                                                 const float* __restrict__ vals) {
    int i = blockIdx.x * blockDim.x + threadIdx.x;
    if (i < NNZ) {
        int r = nz[2 * i];
        int c = nz[2 * i + 1];
        int p = g_col_off[c] + atomicAdd(&g_col_cnt[c], 1);
        g_rows[p] = r;
        g_vals[p] = vals[i];
    }
}

// ---------------- 5. transpose x [B,K] fp32 -> xT [K,B] fp16 ----------------
__global__ void __launch_bounds__(256) k_txpose_x(const float* __restrict__ x) {
    __shared__ float s[32][33];
    int rb = blockIdx.x * 32;       // row (input-dim) base, 20000/32 = 625
    int bb = blockIdx.y * 32;       // batch base, 1024/32 = 32
    int tx = threadIdx.x, ty = threadIdx.y;   // (32, 8)
#pragma unroll
    for (int j = 0; j < 32; j += 8)
        s[ty + j][tx] = x[(size_t)(bb + ty + j) * INPUT_DIM + rb + tx];
    __syncthreads();
#pragma unroll
    for (int j = 0; j < 32; j += 8)
        g_xT[(size_t)(rb + ty + j) * BATCH + bb + tx] = __float2half(s[tx][ty + j]);
}

// ---------------- 6. sparse mm: one block per output column ----------------
__global__ void __launch_bounds__(256) k_spmm(const float* __restrict__ bias) {
    const int u = blockIdx.x;
    const int t = threadIdx.x;
    __shared__ int2 s_rv[256];

    const int start = g_col_off[u];
    const int end   = g_col_off[u + 1];

    float a0 = 0.f, a1 = 0.f, a2 = 0.f, a3 = 0.f;
    const uint2* __restrict__ xp = reinterpret_cast<const uint2*>(g_xT);

    for (int base = start; base < end; base += 256) {
        int n = min(256, end - base);
        if (t < n) {
            int2 rv;
            rv.x = g_rows[base + t];
            rv.y = __float_as_int(g_vals[base + t]);
            s_rv[t] = rv;
        }
        __syncthreads();
#pragma unroll 4
        for (int i = 0; i < n; i++) {
            int2  rv = s_rv[i];
            uint2 d  = xp[rv.x * (BATCH / 4) + t];    // 8 B = 4 fp16 batch elems
            float v  = __int_as_float(rv.y);
            float2 f01 = __half22float2(*reinterpret_cast<__half2*>(&d.x));
            float2 f23 = __half22float2(*reinterpret_cast<__half2*>(&d.y));
            a0 = fmaf(f01.x, v, a0);
            a1 = fmaf(f01.y, v, a1);
            a2 = fmaf(f23.x, v, a2);
            a3 = fmaf(f23.y, v, a3);
        }
        __syncthreads();
    }

    float b = bias[u];
    float4 o;
    o.x = tanhf(a0 + b);
    o.y = tanhf(a1 + b);
    o.z = tanhf(a2 + b);
    o.w = tanhf(a3 + b);
    *reinterpret_cast<float4*>(&g_outT[(size_t)u * BATCH + t * 4]) = o;
}

// ---------------- 7. transpose outT [U,B] -> out [B,U] ----------------
__global__ void __launch_bounds__(256) k_txpose_out(float* __restrict__ out) {
    __shared__ float s[32][33];
    int ub = blockIdx.x * 32;       // 4096/32 = 128
    int bb = blockIdx.y * 32;       // 1024/32 = 32
    int tx = threadIdx.x, ty = threadIdx.y;   // (32, 8)
#pragma unroll
    for (int j = 0; j < 32; j += 8)
        s[ty + j][tx] = g_outT[(size_t)(ub + ty + j) * BATCH + bb + tx];
    __syncthreads();
#pragma unroll
    for (int j = 0; j < 32; j += 8)
        out[(size_t)(bb + ty + j) * UNITS + ub + tx] = s[tx][ty + j];
}

// ---------------- launch ----------------
extern "C" void kernel_launch(void* const* d_in, const int* in_sizes, int n_in,
                              void* d_out, int out_size) {
    const float* x    = (const float*)d_in[0];   // [1024, 20000] fp32
    const float* kv   = (const float*)d_in[1];   // [800000] fp32
    const float* bias = (const float*)d_in[2];   // [4096] fp32
    const int*   nz   = (const int*)d_in[3];     // [800000, 2] int32 (row, col)
    float* out = (float*)d_out;                  // [1024, 4096] fp32

    k_zero<<<(UNITS + 255) / 256, 256>>>();
    k_hist<<<128, 256>>>(nz);
    k_scan<<<1, 1024>>>();
    k_scatter<<<(NNZ + 255) / 256, 256>>>(nz, kv);

    dim3 tb(32, 8);
    k_txpose_x<<<dim3(INPUT_DIM / 32, BATCH / 32), tb>>>(x);

    k_spmm<<<UNITS, 256>>>(bias);

    k_txpose_out<<<dim3(UNITS / 32, BATCH / 32), tb>>>(out);
}

// round 2
// speedup vs baseline: 1.6260x; 1.6260x over previous
#include <cuda_runtime.h>
#include <cuda_fp16.h>

#define INPUT_DIM 20000
#define UNITS     4096
#define NNZ       800000
#define BATCH     1024
#define NB_HIST   64

// ---------------- scratch (no allocations allowed) ----------------
__device__ int    g_col_cnt[UNITS];            // scatter cursors
__device__ int    g_col_off[UNITS + 1];
__device__ int    g_part[NB_HIST * UNITS];     // per-block partial histograms (1 MB)
__device__ int2   g_rv[NNZ];                   // fused (row, val-bits)
__device__ __half g_xT[(size_t)INPUT_DIM * BATCH];   // 41 MB, L2-resident
__device__ float  g_outT[(size_t)UNITS * BATCH];     // 16.8 MB

// ---------------- 1. fused: x transpose (fp32->fp16) + column histogram ----------
// blocks [0, NB_HIST): per-block partial histogram of nonzero columns
// blocks [NB_HIST, NB_HIST + 625*32): 32x32 transpose tiles
__global__ void __launch_bounds__(256) k_combo(const float* __restrict__ x,
                                               const int*   __restrict__ nz) {
    __shared__ int sm[4224];   // 16.9 KB: hist view (4096 ints) or tile view (32x33 f32)
    const int tid = threadIdx.y * 32 + threadIdx.x;

    if (blockIdx.x < NB_HIST) {
        // ---- partial histogram ----
        for (int i = tid; i < UNITS; i += 256) sm[i] = 0;
        __syncthreads();
        const int2* __restrict__ nz2 = reinterpret_cast<const int2*>(nz);
        for (int i = blockIdx.x * 256 + tid; i < NNZ; i += NB_HIST * 256) {
            int2 p = nz2[i];                 // (row, col)
            atomicAdd(&sm[p.y], 1);
        }
        __syncthreads();
        for (int i = tid; i < UNITS; i += 256)
            g_part[blockIdx.x * UNITS + i] = sm[i];
    } else {
        // ---- transpose tile ----
        float (*s)[33] = reinterpret_cast<float(*)[33]>(sm);
        int tb = blockIdx.x - NB_HIST;
        int rb = (tb % 625) * 32;            // input-dim base
        int bb = (tb / 625) * 32;            // batch base
        int tx = threadIdx.x, ty = threadIdx.y;
#pragma unroll
        for (int j = 0; j < 32; j += 8)
            s[ty + j][tx] = x[(size_t)(bb + ty + j) * INPUT_DIM + rb + tx];
        __syncthreads();
#pragma unroll
        for (int j = 0; j < 32; j += 8)
            g_xT[(size_t)(rb + ty + j) * BATCH + bb + tx] = __float2half(s[tx][ty + j]);
    }
}

// ---------------- 2. reduce partials + exclusive scan + reset cursors ------------
__global__ void __launch_bounds__(1024) k_scan() {
    __shared__ int s[1024];
    int t = threadIdx.x;
    int4 c = make_int4(0, 0, 0, 0);
#pragma unroll 8
    for (int p = 0; p < NB_HIST; p++) {
        int4 v = *reinterpret_cast<int4*>(&g_part[p * UNITS + t * 4]);
        c.x += v.x; c.y += v.y; c.z += v.z; c.w += v.w;
    }
    int sum = c.x + c.y + c.z + c.w;
    s[t] = sum;
    __syncthreads();
    for (int off = 1; off < 1024; off <<= 1) {
        int v = (t >= off) ? s[t - off] : 0;
        __syncthreads();
        s[t] += v;
        __syncthreads();
    }
    int o = s[t] - sum;  // exclusive prefix of this group of 4
    g_col_off[t * 4 + 0] = o;  o += c.x;
    g_col_off[t * 4 + 1] = o;  o += c.y;
    g_col_off[t * 4 + 2] = o;  o += c.z;
    g_col_off[t * 4 + 3] = o;
    if (t == 1023) g_col_off[UNITS] = s[1023];
    *reinterpret_cast<int4*>(&g_col_cnt[t * 4]) = make_int4(0, 0, 0, 0);
}

// ---------------- 3. scatter into CSC (4 elems/thread, fused int2 stores) --------
__global__ void __launch_bounds__(256) k_scatter(const int*   __restrict__ nz,
                                                 const float* __restrict__ vals) {
    int i0 = (blockIdx.x * 256 + threadIdx.x) * 4;
    if (i0 + 3 < NNZ) {
        int4 a = *reinterpret_cast<const int4*>(&nz[2 * i0]);       // e0,e1
        int4 b = *reinterpret_cast<const int4*>(&nz[2 * i0 + 4]);   // e2,e3
        float4 v = *reinterpret_cast<const float4*>(&vals[i0]);
        int p0 = g_col_off[a.y] + atomicAdd(&g_col_cnt[a.y], 1);
        int p1 = g_col_off[a.w] + atomicAdd(&g_col_cnt[a.w], 1);
        int p2 = g_col_off[b.y] + atomicAdd(&g_col_cnt[b.y], 1);
        int p3 = g_col_off[b.w] + atomicAdd(&g_col_cnt[b.w], 1);
        g_rv[p0] = make_int2(a.x, __float_as_int(v.x));
        g_rv[p1] = make_int2(a.z, __float_as_int(v.y));
        g_rv[p2] = make_int2(b.x, __float_as_int(v.z));
        g_rv[p3] = make_int2(b.z, __float_as_int(v.w));
    } else {
        for (int i = i0; i < NNZ; i++) {
            int r = nz[2 * i], c = nz[2 * i + 1];
            int p = g_col_off[c] + atomicAdd(&g_col_cnt[c], 1);
            g_rv[p] = make_int2(r, __float_as_int(vals[i]));
        }
    }
}

// ---------------- 4. sparse mm: one block (128 thr) per column, LDG.128 ----------
__global__ void __launch_bounds__(128) k_spmm(const float* __restrict__ bias) {
    const int u = blockIdx.x;
    const int t = threadIdx.x;
    __shared__ int2 s_rv[128];

    const int start = g_col_off[u];
    const int end   = g_col_off[u + 1];

    float a0 = 0.f, a1 = 0.f, a2 = 0.f, a3 = 0.f;
    float a4 = 0.f, a5 = 0.f, a6 = 0.f, a7 = 0.f;
    const uint4* __restrict__ xp = reinterpret_cast<const uint4*>(g_xT);

    for (int base = start; base < end; base += 128) {
        int n = min(128, end - base);
        if (t < n) s_rv[t] = g_rv[base + t];
        __syncthreads();
#pragma unroll 4
        for (int i = 0; i < n; i++) {
            int2  rv = s_rv[i];
            uint4 d  = xp[rv.x * (BATCH / 8) + t];   // 16 B = 8 fp16 batch elems
            float v  = __int_as_float(rv.y);
            float2 f0 = __half22float2(*reinterpret_cast<__half2*>(&d.x));
            float2 f1 = __half22float2(*reinterpret_cast<__half2*>(&d.y));
            float2 f2 = __half22float2(*reinterpret_cast<__half2*>(&d.z));
            float2 f3 = __half22float2(*reinterpret_cast<__half2*>(&d.w));
            a0 = fmaf(f0.x, v, a0);  a1 = fmaf(f0.y, v, a1);
            a2 = fmaf(f1.x, v, a2);  a3 = fmaf(f1.y, v, a3);
            a4 = fmaf(f2.x, v, a4);  a5 = fmaf(f2.y, v, a5);
            a6 = fmaf(f3.x, v, a6);  a7 = fmaf(f3.y, v, a7);
        }
        __syncthreads();
    }

    float b = bias[u];
    float4 o0, o1;
    o0.x = tanhf(a0 + b);  o0.y = tanhf(a1 + b);
    o0.z = tanhf(a2 + b);  o0.w = tanhf(a3 + b);
    o1.x = tanhf(a4 + b);  o1.y = tanhf(a5 + b);
    o1.z = tanhf(a6 + b);  o1.w = tanhf(a7 + b);
    float* op = &g_outT[(size_t)u * BATCH + t * 8];
    *reinterpret_cast<float4*>(op)     = o0;
    *reinterpret_cast<float4*>(op + 4) = o1;
}

// ---------------- 5. transpose outT [U,B] -> out [B,U] ----------------
__global__ void __launch_bounds__(256) k_txpose_out(float* __restrict__ out) {
    __shared__ float s[32][33];
    int ub = blockIdx.x * 32;
    int bb = blockIdx.y * 32;
    int tx = threadIdx.x, ty = threadIdx.y;
#pragma unroll
    for (int j = 0; j < 32; j += 8)
        s[ty + j][tx] = g_outT[(size_t)(ub + ty + j) * BATCH + bb + tx];
    __syncthreads();
#pragma unroll
    for (int j = 0; j < 32; j += 8)
        out[(size_t)(bb + ty + j) * UNITS + ub + tx] = s[tx][ty + j];
}

// ---------------- launch ----------------
extern "C" void kernel_launch(void* const* d_in, const int* in_sizes, int n_in,
                              void* d_out, int out_size) {
    const float* x    = (const float*)d_in[0];   // [1024, 20000] fp32
    const float* kv   = (const float*)d_in[1];   // [800000] fp32
    const float* bias = (const float*)d_in[2];   // [4096] fp32
    const int*   nz   = (const int*)d_in[3];     // [800000, 2] int32 (row, col)
    float* out = (float*)d_out;                  // [1024, 4096] fp32

    dim3 tb(32, 8);
    k_combo<<<NB_HIST + (INPUT_DIM / 32) * (BATCH / 32), tb>>>(x, nz);
    k_scan<<<1, 1024>>>();
    k_scatter<<<(NNZ / 4 + 255) / 256, 256>>>(nz, kv);
    k_spmm<<<UNITS, 128>>>(bias);
    k_txpose_out<<<dim3(UNITS / 32, BATCH / 32), tb>>>(out);
}

// round 3
// speedup vs baseline: 1.7126x; 1.0533x over previous
#include <cuda_runtime.h>
#include <cuda_fp16.h>

#define INPUT_DIM 20000
#define UNITS     4096
#define NNZ       800000
#define BATCH     1024
#define NB_HIST   32

// ---------------- scratch (no allocations allowed) ----------------
__device__ int    g_col_cnt[UNITS];            // scatter cursors
__device__ int    g_col_off[UNITS + 1];
__device__ int    g_part[NB_HIST * UNITS];     // per-block partial histograms
__device__ int2   g_rv[NNZ];                   // (row, half2(v,v) bits)
__device__ __half g_xT[(size_t)INPUT_DIM * BATCH];   // 41 MB, L2-resident
__device__ float  g_outT[(size_t)UNITS * BATCH];     // 16.8 MB

// ---------------- 1. fused: x transpose (fp32->fp16) + column histogram ----------
__global__ void __launch_bounds__(256) k_combo(const float* __restrict__ x,
                                               const int*   __restrict__ nz) {
    __shared__ int sm[4224];   // hist view (4096 ints) or tile view (32x33 f32)
    const int tid = threadIdx.y * 32 + threadIdx.x;

    if (blockIdx.x < NB_HIST) {
        for (int i = tid; i < UNITS; i += 256) sm[i] = 0;
        __syncthreads();
        const int2* __restrict__ nz2 = reinterpret_cast<const int2*>(nz);
        for (int i = blockIdx.x * 256 + tid; i < NNZ; i += NB_HIST * 256) {
            int2 p = nz2[i];
            atomicAdd(&sm[p.y], 1);
        }
        __syncthreads();
        for (int i = tid; i < UNITS; i += 256)
            g_part[blockIdx.x * UNITS + i] = sm[i];
    } else {
        float (*s)[33] = reinterpret_cast<float(*)[33]>(sm);
        int tb = blockIdx.x - NB_HIST;
        int rb = (tb % 625) * 32;
        int bb = (tb / 625) * 32;
        int tx = threadIdx.x, ty = threadIdx.y;
#pragma unroll
        for (int j = 0; j < 32; j += 8)
            s[ty + j][tx] = x[(size_t)(bb + ty + j) * INPUT_DIM + rb + tx];
        __syncthreads();
#pragma unroll
        for (int j = 0; j < 32; j += 8)
            g_xT[(size_t)(rb + ty + j) * BATCH + bb + tx] = __float2half(s[tx][ty + j]);
    }
}

// ---------------- 2. reduce partials + exclusive scan + reset cursors ------------
__global__ void __launch_bounds__(1024) k_scan() {
    __shared__ int s[1024];
    int t = threadIdx.x;
    int4 c = make_int4(0, 0, 0, 0);
#pragma unroll 8
    for (int p = 0; p < NB_HIST; p++) {
        int4 v = *reinterpret_cast<int4*>(&g_part[p * UNITS + t * 4]);
        c.x += v.x; c.y += v.y; c.z += v.z; c.w += v.w;
    }
    int sum = c.x + c.y + c.z + c.w;
    s[t] = sum;
    __syncthreads();
    for (int off = 1; off < 1024; off <<= 1) {
        int v = (t >= off) ? s[t - off] : 0;
        __syncthreads();
        s[t] += v;
        __syncthreads();
    }
    int o = s[t] - sum;
    g_col_off[t * 4 + 0] = o;  o += c.x;
    g_col_off[t * 4 + 1] = o;  o += c.y;
    g_col_off[t * 4 + 2] = o;  o += c.z;
    g_col_off[t * 4 + 3] = o;
    if (t == 1023) g_col_off[UNITS] = s[1023];
    *reinterpret_cast<int4*>(&g_col_cnt[t * 4]) = make_int4(0, 0, 0, 0);
}

// ---------------- 3. scatter into CSC: 8/thread, v -> replicated half2 ----------
__device__ __forceinline__ int pack_h2(float v) {
    unsigned short h = __half_as_ushort(__float2half_rn(v));
    return (int)(((unsigned)h << 16) | (unsigned)h);
}

__global__ void __launch_bounds__(256) k_scatter(const int*   __restrict__ nz,
                                                 const float* __restrict__ vals) {
    int i0 = (blockIdx.x * 256 + threadIdx.x) * 8;
    if (i0 + 7 < NNZ) {
        int4 a = *reinterpret_cast<const int4*>(&nz[2 * i0]);
        int4 b = *reinterpret_cast<const int4*>(&nz[2 * i0 + 4]);
        int4 c = *reinterpret_cast<const int4*>(&nz[2 * i0 + 8]);
        int4 d = *reinterpret_cast<const int4*>(&nz[2 * i0 + 12]);
        float4 v0 = *reinterpret_cast<const float4*>(&vals[i0]);
        float4 v1 = *reinterpret_cast<const float4*>(&vals[i0 + 4]);
        int p0 = g_col_off[a.y] + atomicAdd(&g_col_cnt[a.y], 1);
        int p1 = g_col_off[a.w] + atomicAdd(&g_col_cnt[a.w], 1);
        int p2 = g_col_off[b.y] + atomicAdd(&g_col_cnt[b.y], 1);
        int p3 = g_col_off[b.w] + atomicAdd(&g_col_cnt[b.w], 1);
        int p4 = g_col_off[c.y] + atomicAdd(&g_col_cnt[c.y], 1);
        int p5 = g_col_off[c.w] + atomicAdd(&g_col_cnt[c.w], 1);
        int p6 = g_col_off[d.y] + atomicAdd(&g_col_cnt[d.y], 1);
        int p7 = g_col_off[d.w] + atomicAdd(&g_col_cnt[d.w], 1);
        g_rv[p0] = make_int2(a.x, pack_h2(v0.x));
        g_rv[p1] = make_int2(a.z, pack_h2(v0.y));
        g_rv[p2] = make_int2(b.x, pack_h2(v0.z));
        g_rv[p3] = make_int2(b.z, pack_h2(v0.w));
        g_rv[p4] = make_int2(c.x, pack_h2(v1.x));
        g_rv[p5] = make_int2(c.z, pack_h2(v1.y));
        g_rv[p6] = make_int2(d.x, pack_h2(v1.z));
        g_rv[p7] = make_int2(d.z, pack_h2(v1.w));
    } else {
        for (int i = i0; i < NNZ; i++) {
            int r = nz[2 * i], cc = nz[2 * i + 1];
            int p = g_col_off[cc] + atomicAdd(&g_col_cnt[cc], 1);
            g_rv[p] = make_int2(r, pack_h2(vals[i]));
        }
    }
}

// ---------------- 4. spmm: chunk-4 HFMA2 accumulate, packed f32x2 merge ----------
__global__ void __launch_bounds__(128) k_spmm(const float* __restrict__ bias) {
    const int u = blockIdx.x;
    const int t = threadIdx.x;
    __shared__ int2 s_rv[128];

    const int start = g_col_off[u];
    const int end   = g_col_off[u + 1];

    unsigned long long a0 = 0, a1 = 0, a2 = 0, a3 = 0;   // packed f32x2 accumulators
    const uint4* __restrict__ xp = reinterpret_cast<const uint4*>(g_xT);

    for (int base = start; base < end; base += 128) {
        int n = end - base;
        s_rv[t] = (t < n) ? g_rv[base + t] : make_int2(0, 0);   // zero-pad tail
        __syncthreads();
        int m  = min(128, n);
        int mc = (m + 3) & ~3;    // padded entries are value-zero -> contribute 0
        for (int i = 0; i < mc; i += 4) {
            int4 q01 = *reinterpret_cast<int4*>(&s_rv[i]);      // LDS.128 broadcast
            int4 q23 = *reinterpret_cast<int4*>(&s_rv[i + 2]);
            uint4 d0 = xp[q01.x * (BATCH / 8) + t];
            uint4 d1 = xp[q01.z * (BATCH / 8) + t];
            uint4 d2 = xp[q23.x * (BATCH / 8) + t];
            uint4 d3 = xp[q23.z * (BATCH / 8) + t];
            __half2 v0 = *reinterpret_cast<__half2*>(&q01.y);
            __half2 v1 = *reinterpret_cast<__half2*>(&q01.w);
            __half2 v2 = *reinterpret_cast<__half2*>(&q23.y);
            __half2 v3 = *reinterpret_cast<__half2*>(&q23.w);
#define SLOT(ACC, C)                                                          \
            {                                                                 \
                __half2 p = __hmul2(*reinterpret_cast<__half2*>(&d0.C), v0);  \
                p = __hfma2(*reinterpret_cast<__half2*>(&d1.C), v1, p);       \
                p = __hfma2(*reinterpret_cast<__half2*>(&d2.C), v2, p);       \
                p = __hfma2(*reinterpret_cast<__half2*>(&d3.C), v3, p);       \
                float2 f = __half22float2(p);                                 \
                unsigned long long f64;                                       \
                asm("mov.b64 %0, {%1, %2};" : "=l"(f64) : "f"(f.x), "f"(f.y));\
                asm("add.rn.f32x2 %0, %0, %1;" : "+l"(ACC) : "l"(f64));       \
            }
            SLOT(a0, x)
            SLOT(a1, y)
            SLOT(a2, z)
            SLOT(a3, w)
#undef SLOT
        }
        __syncthreads();
    }

    float b = bias[u];
    float2 f0, f1, f2, f3;
    asm("mov.b64 {%0, %1}, %2;" : "=f"(f0.x), "=f"(f0.y) : "l"(a0));
    asm("mov.b64 {%0, %1}, %2;" : "=f"(f1.x), "=f"(f1.y) : "l"(a1));
    asm("mov.b64 {%0, %1}, %2;" : "=f"(f2.x), "=f"(f2.y) : "l"(a2));
    asm("mov.b64 {%0, %1}, %2;" : "=f"(f3.x), "=f"(f3.y) : "l"(a3));
    float4 o0, o1;
    o0.x = tanhf(f0.x + b);  o0.y = tanhf(f0.y + b);
    o0.z = tanhf(f1.x + b);  o0.w = tanhf(f1.y + b);
    o1.x = tanhf(f2.x + b);  o1.y = tanhf(f2.y + b);
    o1.z = tanhf(f3.x + b);  o1.w = tanhf(f3.y + b);
    float* op = &g_outT[(size_t)u * BATCH + t * 8];
    *reinterpret_cast<float4*>(op)     = o0;
    *reinterpret_cast<float4*>(op + 4) = o1;
}

// ---------------- 5. transpose outT [U,B] -> out [B,U] ----------------
__global__ void __launch_bounds__(256) k_txpose_out(float* __restrict__ out) {
    __shared__ float s[32][33];
    int ub = blockIdx.x * 32;
    int bb = blockIdx.y * 32;
    int tx = threadIdx.x, ty = threadIdx.y;
#pragma unroll
    for (int j = 0; j < 32; j += 8)
        s[ty + j][tx] = g_outT[(size_t)(ub + ty + j) * BATCH + bb + tx];
    __syncthreads();
#pragma unroll
    for (int j = 0; j < 32; j += 8)
        out[(size_t)(bb + ty + j) * UNITS + ub + tx] = s[tx][ty + j];
}

// ---------------- launch ----------------
extern "C" void kernel_launch(void* const* d_in, const int* in_sizes, int n_in,
                              void* d_out, int out_size) {
    const float* x    = (const float*)d_in[0];
    const float* kv   = (const float*)d_in[1];
    const float* bias = (const float*)d_in[2];
    const int*   nz   = (const int*)d_in[3];
    float* out = (float*)d_out;

    dim3 tb(32, 8);
    k_combo<<<NB_HIST + (INPUT_DIM / 32) * (BATCH / 32), tb>>>(x, nz);
    k_scan<<<1, 1024>>>();
    k_scatter<<<(NNZ / 8 + 255) / 256, 256>>>(nz, kv);
    k_spmm<<<UNITS, 128>>>(bias);
    k_txpose_out<<<dim3(UNITS / 32, BATCH / 32), tb>>>(out);
}